// round 2
// baseline (speedup 1.0000x reference)
#include <cuda_runtime.h>
#include <math.h>

// Problem constants
#define BATCH   65536
#define SDIM    256
#define AGENTS  8
#define NACT    16
#define KKER    10
#define HDIM    64
#define ADIM    128          // AGENTS*NACT
#define DDIM    384          // SDIM + ADIM

// Tiling
#define TB       64          // batch rows per CTA
#define NTHREADS 256
#define STRIDE   68          // padded row stride (floats) for [d][i] smem tiles
#define WCHUNK   256         // W1 staging chunk along in-dim

// Shared memory layout (float offsets)
#define XS_OFF   0                       // [384][STRIDE] input tile (states||actions), transposed
#define WS_OFF   (XS_OFF + DDIM*STRIDE)  // [256][STRIDE] weight chunk, transposed; also W3 vector
#define H1_OFF   (WS_OFF + WCHUNK*STRIDE)// [64][STRIDE] hidden 1
#define H2_OFF   (H1_OFF + HDIM*STRIDE)  // [64][STRIDE] hidden 2
#define KEY_OFF  (H2_OFF + HDIM*STRIDE)  // [64]
#define AG_OFF   (KEY_OFF + TB)          // [64][8]
#define ACC_OFF  (AG_OFF + TB*AGENTS)    // [64][8]
#define SMEM_FLOATS (ACC_OFF + TB*AGENTS)
// = 384*68 + 256*68 + 64*68 + 64*68 + 64 + 512 + 512 = 53312 floats = 213248 B

__device__ __forceinline__ float sigmoidf_(float x) {
    return 1.0f / (1.0f + expf(-x));
}

// GEMM: out[i=0..63][j=0..63] = sum_d xs[d][i] * Wg[j][d]
// xs is smem transposed [IN][STRIDE]; Wg is global row-major [64][IN].
// Each thread computes a 4x4 micro-tile. acc is zeroed here.
__device__ __forceinline__ void gemm64(
    const float* __restrict__ xs,
    const float* __restrict__ wg,
    float* __restrict__ ws,
    float acc[4][4], int IN, int tid)
{
    const int tx = (tid & 15) << 2;   // i0
    const int ty = (tid >> 4) << 2;   // j0

    #pragma unroll
    for (int ii = 0; ii < 4; ii++)
        #pragma unroll
        for (int jj = 0; jj < 4; jj++)
            acc[ii][jj] = 0.0f;

    for (int c0 = 0; c0 < IN; c0 += WCHUNK) {
        const int CL = (IN - c0) < WCHUNK ? (IN - c0) : WCHUNK;   // 256/128/64, pow2
        const int cshift = (CL == 256) ? 8 : (CL == 128 ? 7 : 6);

        __syncthreads();   // prior consumers of ws / producers of xs done
        // stage W chunk transposed: ws[d][h] = wg[h][c0+d]; global reads coalesced over d
        for (int idx = tid; idx < (CL << 6); idx += NTHREADS) {
            int dd = idx & (CL - 1);
            int hh = idx >> cshift;
            ws[dd * STRIDE + hh] = __ldg(wg + hh * IN + c0 + dd);
        }
        __syncthreads();

        const float* xp = xs + c0 * STRIDE;
        #pragma unroll 4
        for (int dd = 0; dd < CL; dd++) {
            float4 a = *reinterpret_cast<const float4*>(xp + dd * STRIDE + tx);
            float4 b = *reinterpret_cast<const float4*>(ws + dd * STRIDE + ty);
            acc[0][0] += a.x * b.x; acc[0][1] += a.x * b.y; acc[0][2] += a.x * b.z; acc[0][3] += a.x * b.w;
            acc[1][0] += a.y * b.x; acc[1][1] += a.y * b.y; acc[1][2] += a.y * b.z; acc[1][3] += a.y * b.w;
            acc[2][0] += a.z * b.x; acc[2][1] += a.z * b.y; acc[2][2] += a.z * b.z; acc[2][3] += a.z * b.w;
            acc[3][0] += a.w * b.x; acc[3][1] += a.w * b.y; acc[3][2] += a.w * b.z; acc[3][3] += a.w * b.w;
        }
    }
}

// Epilogue: h[j][i] = relu(acc[i][j] + bias[j]) into smem [64][STRIDE]
__device__ __forceinline__ void epi_relu(
    const float acc[4][4], const float* __restrict__ bias,
    float* __restrict__ hdst, int tid)
{
    const int tx = (tid & 15) << 2;
    const int ty = (tid >> 4) << 2;
    #pragma unroll
    for (int jj = 0; jj < 4; jj++) {
        float bj = __ldg(bias + ty + jj);
        #pragma unroll
        for (int ii = 0; ii < 4; ii++) {
            float v = acc[ii][jj] + bj;
            hdst[(ty + jj) * STRIDE + tx + ii] = v > 0.0f ? v : 0.0f;
        }
    }
}

__global__ void __launch_bounds__(NTHREADS, 1)
qplex_si_kernel(
    const float* __restrict__ states,
    const float* __restrict__ actions,
    const float* __restrict__ kW1, const float* __restrict__ kb1,
    const float* __restrict__ kW2, const float* __restrict__ kb2,
    const float* __restrict__ kW3, const float* __restrict__ kb3,
    const float* __restrict__ aW1, const float* __restrict__ ab1,
    const float* __restrict__ aW2, const float* __restrict__ ab2,
    const float* __restrict__ aW3, const float* __restrict__ ab3,
    const float* __restrict__ cW1, const float* __restrict__ cb1,
    const float* __restrict__ cW2, const float* __restrict__ cb2,
    const float* __restrict__ cW3, const float* __restrict__ cb3,
    float* __restrict__ out)
{
    extern __shared__ float sm[];
    float* xs   = sm + XS_OFF;
    float* ws   = sm + WS_OFF;
    float* h1   = sm + H1_OFF;
    float* h2   = sm + H2_OFF;
    float* keyb = sm + KEY_OFF;
    float* agb  = sm + AG_OFF;
    float* accb = sm + ACC_OFF;

    const int tid = threadIdx.x;
    const int b0  = blockIdx.x * TB;

    // Stage input tile transposed: xs[d][i]. d<256 from states, d>=256 from actions.
    for (int idx = tid; idx < TB * SDIM; idx += NTHREADS) {          // 16384
        int i  = idx >> 8;
        int dd = idx & 255;
        xs[dd * STRIDE + i] = states[(size_t)(b0 + i) * SDIM + dd];
    }
    for (int idx = tid; idx < TB * ADIM; idx += NTHREADS) {          // 8192
        int i  = idx >> 7;
        int dd = idx & 127;
        xs[(SDIM + dd) * STRIDE + i] = actions[(size_t)(b0 + i) * ADIM + dd];
    }
    for (int idx = tid; idx < TB * AGENTS; idx += NTHREADS)
        accb[idx] = 0.0f;
    // gemm64's leading __syncthreads covers these writes.

    float acc[4][4];
    const int i_  = tid & 63;
    const int og_ = (tid >> 6) << 1;   // 0,2,4,6

    for (int k = 0; k < KKER; k++) {
        // ---------------- KEY net: states -> 64 -> 64 -> 1, |.|+1e-10 -------------
        gemm64(xs, kW1 + k * HDIM * SDIM, ws, acc, SDIM, tid);
        epi_relu(acc, kb1 + k * HDIM, h1, tid);
        gemm64(h1, kW2 + k * HDIM * HDIM, ws, acc, HDIM, tid);
        epi_relu(acc, kb2 + k * HDIM, h2, tid);
        __syncthreads();
        if (tid < HDIM) ws[tid] = __ldg(kW3 + k * HDIM + tid);
        __syncthreads();
        if (tid < TB) {
            float s = __ldg(kb3 + k);
            #pragma unroll 8
            for (int h = 0; h < HDIM; h++)
                s += h2[h * STRIDE + tid] * ws[h];
            keyb[tid] = fabsf(s) + 1e-10f;
        }

        // ---------------- AGENTS net: states -> 64 -> 64 -> 8, sigmoid ------------
        gemm64(xs, aW1 + k * HDIM * SDIM, ws, acc, SDIM, tid);
        epi_relu(acc, ab1 + k * HDIM, h1, tid);
        gemm64(h1, aW2 + k * HDIM * HDIM, ws, acc, HDIM, tid);
        epi_relu(acc, ab2 + k * HDIM, h2, tid);
        __syncthreads();
        for (int idx = tid; idx < AGENTS * HDIM; idx += NTHREADS)
            ws[idx] = __ldg(aW3 + k * AGENTS * HDIM + idx);
        __syncthreads();
        {
            float s0 = __ldg(ab3 + k * AGENTS + og_);
            float s1 = __ldg(ab3 + k * AGENTS + og_ + 1);
            const float* w0 = ws + og_ * HDIM;
            const float* w1 = w0 + HDIM;
            #pragma unroll 8
            for (int h = 0; h < HDIM; h++) {
                float x = h2[h * STRIDE + i_];
                s0 += x * w0[h];
                s1 += x * w1[h];
            }
            agb[i_ * AGENTS + og_]     = sigmoidf_(s0);
            agb[i_ * AGENTS + og_ + 1] = sigmoidf_(s1);
        }

        // ---------------- ACTION net: data(384) -> 64 -> 64 -> 8, sigmoid ---------
        gemm64(xs, cW1 + k * HDIM * DDIM, ws, acc, DDIM, tid);
        epi_relu(acc, cb1 + k * HDIM, h1, tid);
        gemm64(h1, cW2 + k * HDIM * HDIM, ws, acc, HDIM, tid);
        epi_relu(acc, cb2 + k * HDIM, h2, tid);
        __syncthreads();
        for (int idx = tid; idx < AGENTS * HDIM; idx += NTHREADS)
            ws[idx] = __ldg(cW3 + k * AGENTS * HDIM + idx);
        __syncthreads();
        {
            float s0 = __ldg(cb3 + k * AGENTS + og_);
            float s1 = __ldg(cb3 + k * AGENTS + og_ + 1);
            const float* w0 = ws + og_ * HDIM;
            const float* w1 = w0 + HDIM;
            #pragma unroll 8
            for (int h = 0; h < HDIM; h++) {
                float x = h2[h * STRIDE + i_];
                s0 += x * w0[h];
                s1 += x * w1[h];
            }
            float kv = keyb[i_];
            accb[i_ * AGENTS + og_]     += kv * agb[i_ * AGENTS + og_]     * sigmoidf_(s0);
            accb[i_ * AGENTS + og_ + 1] += kv * agb[i_ * AGENTS + og_ + 1] * sigmoidf_(s1);
        }
        // next iteration's gemm64 leading __syncthreads is the k-boundary barrier
    }

    __syncthreads();
    for (int idx = tid; idx < TB * AGENTS; idx += NTHREADS)
        out[(size_t)b0 * AGENTS + idx] = accb[idx];
}

extern "C" void kernel_launch(void* const* d_in, const int* in_sizes, int n_in,
                              void* d_out, int out_size)
{
    const float* states  = (const float*)d_in[0];
    const float* actions = (const float*)d_in[1];
    const float* kW1 = (const float*)d_in[2];
    const float* kb1 = (const float*)d_in[3];
    const float* kW2 = (const float*)d_in[4];
    const float* kb2 = (const float*)d_in[5];
    const float* kW3 = (const float*)d_in[6];
    const float* kb3 = (const float*)d_in[7];
    const float* aW1 = (const float*)d_in[8];
    const float* ab1 = (const float*)d_in[9];
    const float* aW2 = (const float*)d_in[10];
    const float* ab2 = (const float*)d_in[11];
    const float* aW3 = (const float*)d_in[12];
    const float* ab3 = (const float*)d_in[13];
    const float* cW1 = (const float*)d_in[14];
    const float* cb1 = (const float*)d_in[15];
    const float* cW2 = (const float*)d_in[16];
    const float* cb2 = (const float*)d_in[17];
    const float* cW3 = (const float*)d_in[18];
    const float* cb3 = (const float*)d_in[19];
    float* out = (float*)d_out;

    const size_t smem_bytes = (size_t)SMEM_FLOATS * sizeof(float);  // 213248
    cudaFuncSetAttribute(qplex_si_kernel,
                         cudaFuncAttributeMaxDynamicSharedMemorySize,
                         (int)smem_bytes);

    qplex_si_kernel<<<BATCH / TB, NTHREADS, smem_bytes>>>(
        states, actions,
        kW1, kb1, kW2, kb2, kW3, kb3,
        aW1, ab1, aW2, ab2, aW3, ab3,
        cW1, cb1, cW2, cb2, cW3, cb3,
        out);
}

// round 5
// speedup vs baseline: 2.0600x; 2.0600x over previous
#include <cuda_runtime.h>
#include <cstdint>
#include <math.h>

#define SDIM 256
#define ADIM 128
#define DDIM 384
#define HDIM 64
#define KKER 10
#define TB   128
#define NT   128

#define XS_O 0u
#define XS_ST 260
#define H_O   33280u
#define H_ST  68
#define WT_O  41984u
#define WT_CH 2304u
#define WT_ST 36
#define XA_O  46592u
#define XA_CH 4608u
#define XA_ST 36
#define W3_O  55808u
#define W3_ST 68
#define B_O   56352u
#define OB_O  56480u
#define SMEMF 57504u   // *4 = 230016 B

__device__ __forceinline__ uint32_t tf32b(float x) {
    uint32_t u; asm("cvt.rna.tf32.f32 %0, %1;" : "=r"(u) : "f"(x)); return u;
}
__device__ __forceinline__ float sigf(float x) { return 1.0f / (1.0f + __expf(-x)); }

__device__ __forceinline__ void mma8(float c[4], uint32_t a0, uint32_t a1,
                                     uint32_t a2, uint32_t a3, uint32_t b0, uint32_t b1) {
    asm volatile("mma.sync.aligned.m16n8k8.row.col.f32.tf32.tf32.f32 "
                 "{%0,%1,%2,%3}, {%4,%5,%6,%7}, {%8,%9}, {%0,%1,%2,%3};"
                 : "+f"(c[0]), "+f"(c[1]), "+f"(c[2]), "+f"(c[3])
                 : "r"(a0), "r"(a1), "r"(a2), "r"(a3), "r"(b0), "r"(b1));
}
__device__ __forceinline__ void lda(uint32_t a[4], const float* base, int st,
                                    int row, int col, int g, int t) {
    const float* p = base + (row + g) * st + col + t;
    a[0] = __float_as_uint(p[0]);
    a[1] = __float_as_uint(p[8 * st]);
    a[2] = __float_as_uint(p[4]);
    a[3] = __float_as_uint(p[8 * st + 4]);
}
__device__ __forceinline__ void stage_w(const float* __restrict__ g, int IN, int c0,
                                        float* __restrict__ dst, int tid) {
    #pragma unroll
    for (int jj = 0; jj < 4; jj++) {
        int idx = tid + NT * jj, o = idx >> 3, d4 = idx & 7;
        float4 v = *reinterpret_cast<const float4*>(g + o * IN + c0 + (d4 << 2));
        *reinterpret_cast<uint4*>(dst + o * WT_ST + (d4 << 2)) =
            make_uint4(tf32b(v.x), tf32b(v.y), tf32b(v.z), tf32b(v.w));
    }
}
__device__ __forceinline__ void stage_xa(const float* __restrict__ act, int b0, int c0,
                                         float* __restrict__ dst, int tid) {
    #pragma unroll
    for (int jj = 0; jj < 8; jj++) {
        int idx = tid + NT * jj, r = idx >> 3, d4 = idx & 7;
        float4 v = *reinterpret_cast<const float4*>(act + (size_t)(b0 + r) * ADIM + c0 + (d4 << 2));
        *reinterpret_cast<uint4*>(dst + r * XA_ST + (d4 << 2)) =
            make_uint4(tf32b(v.x), tf32b(v.y), tf32b(v.z), tf32b(v.w));
    }
}
__device__ __forceinline__ void mma_chunk(const float* __restrict__ A, int Ast, int colb,
                                          const float* __restrict__ wt,
                                          float acc[2][8][4], int wbase, int g, int t) {
    #pragma unroll
    for (int s = 0; s < 4; s++) {
        uint32_t a0[4], a1[4];
        lda(a0, A, Ast, wbase,      colb + 8 * s, g, t);
        lda(a1, A, Ast, wbase + 16, colb + 8 * s, g, t);
        #pragma unroll
        for (int nt = 0; nt < 8; nt++) {
            const float* bp = wt + (nt * 8 + g) * WT_ST + 8 * s + t;
            uint32_t b0 = __float_as_uint(bp[0]), b1 = __float_as_uint(bp[4]);
            mma8(acc[0][nt], a0[0], a0[1], a0[2], a0[3], b0, b1);
            mma8(acc[1][nt], a1[0], a1[1], a1[2], a1[3], b0, b1);
        }
    }
}
__device__ __forceinline__ void zacc(float acc[2][8][4]) {
    #pragma unroll
    for (int m = 0; m < 2; m++)
        #pragma unroll
        for (int n = 0; n < 8; n++)
            #pragma unroll
            for (int i = 0; i < 4; i++) acc[m][n][i] = 0.0f;
}
__device__ __forceinline__ void epi_h(const float acc[2][8][4], float* __restrict__ h,
                                      const float* __restrict__ bias, int wbase, int g, int t) {
    #pragma unroll
    for (int mt = 0; mt < 2; mt++) {
        int r0 = wbase + 16 * mt + g;
        #pragma unroll
        for (int nt = 0; nt < 8; nt++) {
            int c0 = 8 * nt + 2 * t;
            float b0 = bias[c0], b1 = bias[c0 + 1];
            *reinterpret_cast<uint2*>(h + r0 * H_ST + c0) =
                make_uint2(tf32b(fmaxf(acc[mt][nt][0] + b0, 0.f)), tf32b(fmaxf(acc[mt][nt][1] + b1, 0.f)));
            *reinterpret_cast<uint2*>(h + (r0 + 8) * H_ST + c0) =
                make_uint2(tf32b(fmaxf(acc[mt][nt][2] + b0, 0.f)), tf32b(fmaxf(acc[mt][nt][3] + b1, 0.f)));
        }
    }
}

__global__ void __launch_bounds__(NT, 1)
qplex_mma_kernel(
    const float* __restrict__ states, const float* __restrict__ actions,
    const float* __restrict__ kW1, const float* __restrict__ kb1,
    const float* __restrict__ kW2, const float* __restrict__ kb2,
    const float* __restrict__ kW3, const float* __restrict__ kb3,
    const float* __restrict__ aW1, const float* __restrict__ ab1,
    const float* __restrict__ aW2, const float* __restrict__ ab2,
    const float* __restrict__ aW3, const float* __restrict__ ab3,
    const float* __restrict__ cW1, const float* __restrict__ cb1,
    const float* __restrict__ cW2, const float* __restrict__ cb2,
    const float* __restrict__ cW3, const float* __restrict__ cb3,
    float* __restrict__ out)
{
    extern __shared__ float sm[];
    float* xs = sm + XS_O;  float* h  = sm + H_O;   float* wt = sm + WT_O;
    float* xa = sm + XA_O;  float* w3t = sm + W3_O; float* bs = sm + B_O;
    float* ob = sm + OB_O;

    const int tid = threadIdx.x, lane = tid & 31;
    const int g = lane >> 2, t = lane & 3;
    const int wbase = (tid >> 5) << 5;
    const int b0 = blockIdx.x * TB;

    #pragma unroll 4
    for (int jj = 0; jj < 64; jj++) {
        int idx = tid + NT * jj, r = idx >> 6, d4 = idx & 63;
        float4 v = *reinterpret_cast<const float4*>(states + (size_t)(b0 + r) * SDIM + (d4 << 2));
        *reinterpret_cast<uint4*>(xs + r * XS_ST + (d4 << 2)) =
            make_uint4(tf32b(v.x), tf32b(v.y), tf32b(v.z), tf32b(v.w));
    }

    const float* W1s[3] = {kW1, aW1, cW1};
    const float* B1s[3] = {kb1, ab1, cb1};
    const float* W2s[3] = {kW2, aW2, cW2};
    const float* B2s[3] = {kb2, ab2, cb2};

    float acc[2][8][4], keyr = 0.f, agr[8], accr[8];
    #pragma unroll
    for (int o = 0; o < 8; o++) { accr[o] = 0.f; agr[o] = 0.f; }

    for (int k = 0; k < KKER; k++) {
        for (int net = 0; net < 3; net++) {
            const int IN = (net == 2) ? DDIM : SDIM;
            const int NCH = IN >> 5;
            const float* W1k = W1s[net] + (size_t)k * HDIM * IN;

            __syncthreads();                       // protect wt/w3t from prior readers
            if (tid < 64) {
                bs[tid]      = __ldg(B1s[net] + k * HDIM + tid);
                bs[64 + tid] = __ldg(B2s[net] + k * HDIM + tid);
            }
            stage_w(W1k, IN, 0,  wt,         tid);
            stage_w(W1k, IN, 32, wt + WT_CH, tid);
            __syncthreads();

            // -------- layer 1 --------
            zacc(acc);
            for (int j = 0; j < NCH; j++) {
                const float* wtb = wt + (j & 1) * WT_CH;
                if (32 * j < SDIM) mma_chunk(xs, XS_ST, 32 * j, wtb, acc, wbase, g, t);
                else               mma_chunk(xa + (j & 1) * XA_CH, XA_ST, 0, wtb, acc, wbase, g, t);
                __syncthreads();
                int jn = j + 2;
                if (jn < NCH) {
                    stage_w(W1k, IN, 32 * jn, wt + (jn & 1) * WT_CH, tid);
                    if (32 * jn >= SDIM)
                        stage_xa(actions, b0, 32 * jn - SDIM, xa + (jn & 1) * XA_CH, tid);
                }
            }
            epi_h(acc, h, bs, wbase, g, t);

            // -------- stage W2 + W3 --------
            const float* W2k = W2s[net] + (size_t)k * HDIM * HDIM;
            stage_w(W2k, HDIM, 0,  wt,         tid);
            stage_w(W2k, HDIM, 32, wt + WT_CH, tid);
            if (net == 0) {
                const float* g3 = kW3 + (size_t)k * HDIM;
                if (tid < 16) {
                    float4 v = *reinterpret_cast<const float4*>(g3 + (tid << 2));
                    *reinterpret_cast<uint4*>(w3t + (tid << 2)) =
                        make_uint4(tf32b(v.x), tf32b(v.y), tf32b(v.z), tf32b(v.w));
                } else {
                    int idx = tid - 16, o = 1 + (idx >> 4), d4 = idx & 15;
                    *reinterpret_cast<uint4*>(w3t + o * W3_ST + (d4 << 2)) = make_uint4(0u, 0u, 0u, 0u);
                }
            } else {
                const float* g3 = ((net == 1) ? aW3 : cW3) + (size_t)k * 8 * HDIM;
                int o = tid >> 4, d4 = tid & 15;
                float4 v = *reinterpret_cast<const float4*>(g3 + o * HDIM + (d4 << 2));
                *reinterpret_cast<uint4*>(w3t + o * W3_ST + (d4 << 2)) =
                    make_uint4(tf32b(v.x), tf32b(v.y), tf32b(v.z), tf32b(v.w));
            }
            __syncthreads();

            // -------- layer 2 --------
            zacc(acc);
            mma_chunk(h, H_ST, 0,  wt,         acc, wbase, g, t);
            mma_chunk(h, H_ST, 32, wt + WT_CH, acc, wbase, g, t);
            epi_h(acc, h, bs + 64, wbase, g, t);   // own-warp rows only

            // -------- layer 3 (N=8) --------
            float a3[2][4];
            #pragma unroll
            for (int m = 0; m < 2; m++)
                #pragma unroll
                for (int i = 0; i < 4; i++) a3[m][i] = 0.f;
            #pragma unroll
            for (int s = 0; s < 8; s++) {
                uint32_t a0[4], a1[4];
                lda(a0, h, H_ST, wbase,      8 * s, g, t);
                lda(a1, h, H_ST, wbase + 16, 8 * s, g, t);
                const float* bp = w3t + g * W3_ST + 8 * s + t;
                uint32_t b0 = __float_as_uint(bp[0]), b1 = __float_as_uint(bp[4]);
                mma8(a3[0], a0[0], a0[1], a0[2], a0[3], b0, b1);
                mma8(a3[1], a1[0], a1[1], a1[2], a1[3], b0, b1);
            }
            #pragma unroll
            for (int mt = 0; mt < 2; mt++) {
                int r0 = wbase + 16 * mt + g;
                *reinterpret_cast<float2*>(ob + r0 * 8 + 2 * t)       = make_float2(a3[mt][0], a3[mt][1]);
                *reinterpret_cast<float2*>(ob + (r0 + 8) * 8 + 2 * t) = make_float2(a3[mt][2], a3[mt][3]);
            }
            __syncwarp();
            {
                const float* orow = ob + tid * 8;   // row tid owned by this warp
                if (net == 0) {
                    keyr = fabsf(orow[0] + __ldg(kb3 + k)) + 1e-10f;
                } else if (net == 1) {
                    #pragma unroll
                    for (int o = 0; o < 8; o++)
                        agr[o] = sigf(orow[o] + __ldg(ab3 + k * 8 + o));
                } else {
                    #pragma unroll
                    for (int o = 0; o < 8; o++)
                        accr[o] += keyr * agr[o] * sigf(orow[o] + __ldg(cb3 + k * 8 + o));
                }
            }
            __syncwarp();
        }
    }

    float4* op = reinterpret_cast<float4*>(out + (size_t)(b0 + tid) * 8);
    op[0] = make_float4(accr[0], accr[1], accr[2], accr[3]);
    op[1] = make_float4(accr[4], accr[5], accr[6], accr[7]);
}

extern "C" void kernel_launch(void* const* d_in, const int* in_sizes, int n_in,
                              void* d_out, int out_size)
{
    const float* states  = (const float*)d_in[0];
    const float* actions = (const float*)d_in[1];
    const float* kW1 = (const float*)d_in[2];  const float* kb1 = (const float*)d_in[3];
    const float* kW2 = (const float*)d_in[4];  const float* kb2 = (const float*)d_in[5];
    const float* kW3 = (const float*)d_in[6];  const float* kb3 = (const float*)d_in[7];
    const float* aW1 = (const float*)d_in[8];  const float* ab1 = (const float*)d_in[9];
    const float* aW2 = (const float*)d_in[10]; const float* ab2 = (const float*)d_in[11];
    const float* aW3 = (const float*)d_in[12]; const float* ab3 = (const float*)d_in[13];
    const float* cW1 = (const float*)d_in[14]; const float* cb1 = (const float*)d_in[15];
    const float* cW2 = (const float*)d_in[16]; const float* cb2 = (const float*)d_in[17];
    const float* cW3 = (const float*)d_in[18]; const float* cb3 = (const float*)d_in[19];
    float* out = (float*)d_out;

    const size_t smem = SMEMF * sizeof(float);
    cudaFuncSetAttribute(qplex_mma_kernel,
                         cudaFuncAttributeMaxDynamicSharedMemorySize, (int)smem);
    qplex_mma_kernel<<<65536 / TB, NT, smem>>>(
        states, actions, kW1, kb1, kW2, kb2, kW3, kb3,
        aW1, ab1, aW2, ab2, aW3, ab3, cW1, cb1, cW2, cb2, cW3, cb3, out);
}

// round 6
// speedup vs baseline: 2.7678x; 1.3436x over previous
#include <cuda_runtime.h>
#include <cstdint>
#include <math.h>

#define SDIM 256
#define ADIM 128
#define HDIM 64
#define KKER 10
#define TB   128
#define NT   512

// float offsets in dynamic smem
#define XS_O  0u        // 32 cg x 128 rows x 8  = 32768
#define H_O   32768u    //  8 cg x 128 x 8       = 8192
#define WT_O  40960u    // 2 buffers x (4 cg x 64 x 8) = 4096
#define WT_CH 2048u
#define XA_O  45056u    // 2 buffers x (4 cg x 128 x 8) = 8192
#define XA_CH 4096u
#define W3_O  53248u    // 8 cg x 8 x 8 = 512
#define B_O   53760u    // 128 (bias1|bias2)
#define OB_O  53888u    // 128 x 8 = 1024
#define SMEMF 54912u    // *4 = 219648 bytes

__device__ __forceinline__ uint32_t tf32b(float x) {
    uint32_t u; asm("cvt.rna.tf32.f32 %0, %1;" : "=r"(u) : "f"(x)); return u;
}
__device__ __forceinline__ float tf32f(float x) { return __uint_as_float(tf32b(x)); }
__device__ __forceinline__ float sigf(float x) { return 1.0f / (1.0f + __expf(-x)); }

__device__ __forceinline__ void mma8(float c[4], uint32_t a0, uint32_t a1,
                                     uint32_t a2, uint32_t a3, uint32_t b0, uint32_t b1) {
    asm volatile("mma.sync.aligned.m16n8k8.row.col.f32.tf32.tf32.f32 "
                 "{%0,%1,%2,%3}, {%4,%5,%6,%7}, {%8,%9}, {%0,%1,%2,%3};"
                 : "+f"(c[0]), "+f"(c[1]), "+f"(c[2]), "+f"(c[3])
                 : "r"(a0), "r"(a1), "r"(a2), "r"(a3), "r"(b0), "r"(b1));
}

// interleaved-pair scatter: element c within 8-group lives at ((c&3)<<1)|((c>>2)&1)
// stage [64 out x 32 k] weight chunk into tiled [4cg][64][8]; 512 thr, 1 float4 each
__device__ __forceinline__ void stage_w(const float* __restrict__ g, int IN, int c0,
                                        float* __restrict__ dst, int tid) {
    int o = tid >> 3, j = tid & 7;
    float4 v = *reinterpret_cast<const float4*>(g + o * IN + c0 + (j << 2));
    float* d = dst + (((j >> 1) * 64 + o) << 3) + (j & 1);
    d[0] = tf32f(v.x); d[2] = tf32f(v.y); d[4] = tf32f(v.z); d[6] = tf32f(v.w);
}
// stage [128 x 32] action chunk into tiled [4cg][128][8]
__device__ __forceinline__ void stage_xa(const float* __restrict__ act, int b0, int c0,
                                         float* __restrict__ dst, int tid) {
    #pragma unroll
    for (int jj = 0; jj < 2; jj++) {
        int idx = tid + NT * jj, r = idx >> 3, j = idx & 7;
        float4 v = *reinterpret_cast<const float4*>(act + (size_t)(b0 + r) * ADIM + c0 + (j << 2));
        float* d = dst + (((j >> 1) * 128 + r) << 3) + (j & 1);
        d[0] = tf32f(v.x); d[2] = tf32f(v.y); d[4] = tf32f(v.z); d[6] = tf32f(v.w);
    }
}

// one 32-k chunk: warp computes m16 x n32; A tiled [cg][128][8], B tiled [cg][64][8]
__device__ __forceinline__ void mma_chunk(const float* __restrict__ A, int cg0,
                                          const float* __restrict__ wtb,
                                          float acc[4][4], int wbase, int ng0, int g, int t) {
    #pragma unroll
    for (int s = 0; s < 4; s++) {
        const float* ap = A + (((cg0 + s) * 128 + wbase + g) << 3) + 2 * t;
        float2 fa = *reinterpret_cast<const float2*>(ap);
        float2 fb = *reinterpret_cast<const float2*>(ap + 64);
        uint32_t a0 = __float_as_uint(fa.x), a2 = __float_as_uint(fa.y);
        uint32_t a1 = __float_as_uint(fb.x), a3 = __float_as_uint(fb.y);
        #pragma unroll
        for (int nt = 0; nt < 4; nt++) {
            const float* bp = wtb + ((s * 64 + (ng0 + nt) * 8 + g) << 3) + 2 * t;
            float2 b = *reinterpret_cast<const float2*>(bp);
            mma8(acc[nt], a0, a1, a2, a3, __float_as_uint(b.x), __float_as_uint(b.y));
        }
    }
}
__device__ __forceinline__ void zacc(float acc[4][4]) {
    #pragma unroll
    for (int n = 0; n < 4; n++)
        #pragma unroll
        for (int i = 0; i < 4; i++) acc[n][i] = 0.0f;
}
// bias+relu+tf32 into tiled h
__device__ __forceinline__ void epi_h(const float acc[4][4], float* __restrict__ h,
                                      const float* __restrict__ bias,
                                      int wbase, int ng0, int g, int t) {
    int cc0 = 2 * t, cc1 = 2 * t + 1;
    int p0 = ((cc0 & 3) << 1) | ((cc0 >> 2) & 1);
    int p1 = ((cc1 & 3) << 1) | ((cc1 >> 2) & 1);
    #pragma unroll
    for (int nt = 0; nt < 4; nt++) {
        int ng = ng0 + nt;
        float b0 = bias[ng * 8 + cc0], b1 = bias[ng * 8 + cc1];
        float* hp = h + ((ng * 128 + wbase + g) << 3);
        hp[p0]      = tf32f(fmaxf(acc[nt][0] + b0, 0.f));
        hp[p1]      = tf32f(fmaxf(acc[nt][1] + b1, 0.f));
        hp[64 + p0] = tf32f(fmaxf(acc[nt][2] + b0, 0.f));
        hp[64 + p1] = tf32f(fmaxf(acc[nt][3] + b1, 0.f));
    }
}

__global__ void __launch_bounds__(NT, 1)
qplex_mma2_kernel(
    const float* __restrict__ states, const float* __restrict__ actions,
    const float* __restrict__ kW1, const float* __restrict__ kb1,
    const float* __restrict__ kW2, const float* __restrict__ kb2,
    const float* __restrict__ kW3, const float* __restrict__ kb3,
    const float* __restrict__ aW1, const float* __restrict__ ab1,
    const float* __restrict__ aW2, const float* __restrict__ ab2,
    const float* __restrict__ aW3, const float* __restrict__ ab3,
    const float* __restrict__ cW1, const float* __restrict__ cb1,
    const float* __restrict__ cW2, const float* __restrict__ cb2,
    const float* __restrict__ cW3, const float* __restrict__ cb3,
    float* __restrict__ out)
{
    extern __shared__ float sm[];
    float* xs = sm + XS_O;   float* h = sm + H_O;    float* wt = sm + WT_O;
    float* xa = sm + XA_O;   float* w3t = sm + W3_O; float* bs = sm + B_O;
    float* ob = sm + OB_O;

    const int tid = threadIdx.x, lane = tid & 31;
    const int g = lane >> 2, t = lane & 3;
    const int wid = tid >> 5, rg = wid >> 1, nh = wid & 1;
    const int wbase = rg << 4, ng0 = nh << 2;
    const int b0 = blockIdx.x * TB;

    // stage states into tiled xs (once)
    #pragma unroll 4
    for (int jj = 0; jj < 16; jj++) {
        int idx = tid + NT * jj, r = idx >> 6, c4 = idx & 63;
        float4 v = *reinterpret_cast<const float4*>(states + (size_t)(b0 + r) * SDIM + (c4 << 2));
        float* d = xs + (((c4 >> 1) * 128 + r) << 3) + (c4 & 1);
        d[0] = tf32f(v.x); d[2] = tf32f(v.y); d[4] = tf32f(v.z); d[6] = tf32f(v.w);
    }

    const float* W1s[3] = {kW1, aW1, cW1};
    const float* B1s[3] = {kb1, ab1, cb1};
    const float* W2s[3] = {kW2, aW2, cW2};
    const float* B2s[3] = {kb2, ab2, cb2};

    float acc[4][4], keyr = 0.f, agr[8], accr[8];
    #pragma unroll
    for (int o = 0; o < 8; o++) { accr[o] = 0.f; agr[o] = 0.f; }

    for (int k = 0; k < KKER; k++) {
        for (int net = 0; net < 3; net++) {
            const int IN = (net == 2) ? (SDIM + ADIM) : SDIM;
            const int NCH = IN >> 5;
            const float* W1k = W1s[net] + (size_t)k * HDIM * IN;

            __syncthreads();
            if (tid < 64) {
                bs[tid]      = __ldg(B1s[net] + k * HDIM + tid);
                bs[64 + tid] = __ldg(B2s[net] + k * HDIM + tid);
            }
            stage_w(W1k, IN, 0,  wt,         tid);
            stage_w(W1k, IN, 32, wt + WT_CH, tid);
            __syncthreads();

            // ---- layer 1 ----
            zacc(acc);
            for (int j = 0; j < NCH; j++) {
                if (j < 8) mma_chunk(xs, j << 2, wt + (j & 1) * WT_CH, acc, wbase, ng0, g, t);
                else       mma_chunk(xa + (j & 1) * XA_CH, 0, wt + (j & 1) * WT_CH, acc, wbase, ng0, g, t);
                __syncthreads();
                int jn = j + 2;
                if (jn < NCH) {
                    stage_w(W1k, IN, jn << 5, wt + (jn & 1) * WT_CH, tid);
                    if (jn >= 8) stage_xa(actions, b0, (jn - 8) << 5, xa + (jn & 1) * XA_CH, tid);
                }
            }
            epi_h(acc, h, bs, wbase, ng0, g, t);

            // ---- stage W2 + W3 ----
            const float* W2k = W2s[net] + (size_t)k * HDIM * HDIM;
            stage_w(W2k, HDIM, 0,  wt,         tid);
            stage_w(W2k, HDIM, 32, wt + WT_CH, tid);
            if (tid < 128) {
                int o = tid >> 4, c4 = tid & 15;
                float4 v;
                if (net == 0) {
                    const float* g3 = kW3 + (size_t)k * HDIM;
                    v = (o == 0) ? *reinterpret_cast<const float4*>(g3 + (c4 << 2))
                                 : make_float4(0.f, 0.f, 0.f, 0.f);
                } else {
                    const float* g3 = ((net == 1) ? aW3 : cW3) + (size_t)k * 8 * HDIM;
                    v = *reinterpret_cast<const float4*>(g3 + o * HDIM + (c4 << 2));
                }
                float* d = w3t + (((c4 >> 1) * 8 + o) << 3) + (c4 & 1);
                d[0] = tf32f(v.x); d[2] = tf32f(v.y); d[4] = tf32f(v.z); d[6] = tf32f(v.w);
            }
            __syncthreads();

            // ---- layer 2 ----
            zacc(acc);
            mma_chunk(h, 0, wt,         acc, wbase, ng0, g, t);
            mma_chunk(h, 4, wt + WT_CH, acc, wbase, ng0, g, t);
            __syncthreads();                    // all reads of h done
            epi_h(acc, h, bs + 64, wbase, ng0, g, t);
            __syncthreads();                    // h complete for L3

            // ---- layer 3 (m16 x n8, even warps only) ----
            if (nh == 0) {
                float a3[4] = {0.f, 0.f, 0.f, 0.f};
                #pragma unroll
                for (int s = 0; s < 8; s++) {
                    const float* ap = h + (((s * 128) + wbase + g) << 3) + 2 * t;
                    float2 fa = *reinterpret_cast<const float2*>(ap);
                    float2 fb = *reinterpret_cast<const float2*>(ap + 64);
                    const float* bp = w3t + (((s * 8) + g) << 3) + 2 * t;
                    float2 b = *reinterpret_cast<const float2*>(bp);
                    mma8(a3, __float_as_uint(fa.x), __float_as_uint(fb.x),
                             __float_as_uint(fa.y), __float_as_uint(fb.y),
                             __float_as_uint(b.x), __float_as_uint(b.y));
                }
                int r0 = wbase + g;
                *reinterpret_cast<float2*>(ob + r0 * 8 + 2 * t)       = make_float2(a3[0], a3[1]);
                *reinterpret_cast<float2*>(ob + (r0 + 8) * 8 + 2 * t) = make_float2(a3[2], a3[3]);
            }
            __syncthreads();
            if (tid < 128) {
                const float* orow = ob + tid * 8;
                if (net == 0) {
                    keyr = fabsf(orow[0] + __ldg(kb3 + k)) + 1e-10f;
                } else if (net == 1) {
                    #pragma unroll
                    for (int o = 0; o < 8; o++)
                        agr[o] = sigf(orow[o] + __ldg(ab3 + k * 8 + o));
                } else {
                    #pragma unroll
                    for (int o = 0; o < 8; o++)
                        accr[o] += keyr * agr[o] * sigf(orow[o] + __ldg(cb3 + k * 8 + o));
                }
            }
        }
    }

    if (tid < 128) {
        float4* op = reinterpret_cast<float4*>(out + (size_t)(b0 + tid) * 8);
        op[0] = make_float4(accr[0], accr[1], accr[2], accr[3]);
        op[1] = make_float4(accr[4], accr[5], accr[6], accr[7]);
    }
}

extern "C" void kernel_launch(void* const* d_in, const int* in_sizes, int n_in,
                              void* d_out, int out_size)
{
    const float* states  = (const float*)d_in[0];
    const float* actions = (const float*)d_in[1];
    const float* kW1 = (const float*)d_in[2];  const float* kb1 = (const float*)d_in[3];
    const float* kW2 = (const float*)d_in[4];  const float* kb2 = (const float*)d_in[5];
    const float* kW3 = (const float*)d_in[6];  const float* kb3 = (const float*)d_in[7];
    const float* aW1 = (const float*)d_in[8];  const float* ab1 = (const float*)d_in[9];
    const float* aW2 = (const float*)d_in[10]; const float* ab2 = (const float*)d_in[11];
    const float* aW3 = (const float*)d_in[12]; const float* ab3 = (const float*)d_in[13];
    const float* cW1 = (const float*)d_in[14]; const float* cb1 = (const float*)d_in[15];
    const float* cW2 = (const float*)d_in[16]; const float* cb2 = (const float*)d_in[17];
    const float* cW3 = (const float*)d_in[18]; const float* cb3 = (const float*)d_in[19];
    float* out = (float*)d_out;

    const size_t smem = SMEMF * sizeof(float);   // 219648
    cudaFuncSetAttribute(qplex_mma2_kernel,
                         cudaFuncAttributeMaxDynamicSharedMemorySize, (int)smem);
    qplex_mma2_kernel<<<65536 / TB, NT, smem>>>(
        states, actions, kW1, kb1, kW2, kb2, kW3, kb3,
        aW1, ab1, aW2, ab2, aW3, ab3, cW1, cb1, cW2, cb2, cW3, cb3, out);
}